// round 6
// baseline (speedup 1.0000x reference)
#include <cuda_runtime.h>
#include <cuda_bf16.h>
#include <cstdint>

typedef unsigned long long u64;

// ---------------- static scratch ----------------
// activation planes, layout (p, b, c): elem (p*128+b)*256+c, bf16 hi/lo split
__device__ __align__(16) __nv_bfloat16 g_hA[16777216];  // 33.5 MB (512 pos)
__device__ __align__(16) __nv_bfloat16 g_lA[16777216];  // 33.5 MB
__device__ __align__(16) __nv_bfloat16 g_hB[8388608];   // 16.8 MB (256 pos)
__device__ __align__(16) __nv_bfloat16 g_lB[8388608];   // 16.8 MB
__device__ __align__(16) float g_part[4194304];         // 16.8 MB split-K partials

// ---------------- helpers ----------------
__device__ __forceinline__ uint32_t s2u(const void* p) {
    uint32_t a;
    asm("{\n\t.reg .u64 t;\n\tcvta.to.shared.u64 t, %1;\n\tcvt.u32.u64 %0, t;\n\t}" : "=r"(a) : "l"(p));
    return a;
}
// pack: first arg -> low half, second -> high half
__device__ __forceinline__ uint32_t packbf(float lo, float hi) {
    uint32_t r;
    asm("cvt.rn.bf16x2.f32 %0, %1, %2;" : "=r"(r) : "f"(hi), "f"(lo));
    return r;
}
__device__ __forceinline__ void split2(float x0, float x1, uint32_t& hi, uint32_t& lo) {
    uint32_t h = packbf(x0, x1);
    __nv_bfloat162 h2 = *(__nv_bfloat162*)&h;
    lo = packbf(x0 - __bfloat162float(h2.x), x1 - __bfloat162float(h2.y));
    hi = h;
}
__device__ __forceinline__ void ldsm4(uint32_t* r, uint32_t addr) {
    asm volatile("ldmatrix.sync.aligned.m8n8.x4.shared.b16 {%0,%1,%2,%3}, [%4];"
        : "=r"(r[0]), "=r"(r[1]), "=r"(r[2]), "=r"(r[3]) : "r"(addr));
}
__device__ __forceinline__ void mma16816(float* d, const uint32_t* a, uint32_t b0, uint32_t b1) {
    asm volatile("mma.sync.aligned.m16n8k16.row.col.f32.bf16.bf16.f32 "
        "{%0,%1,%2,%3}, {%4,%5,%6,%7}, {%8,%9}, {%0,%1,%2,%3};"
        : "+f"(d[0]), "+f"(d[1]), "+f"(d[2]), "+f"(d[3])
        : "r"(a[0]), "r"(a[1]), "r"(a[2]), "r"(a[3]), "r"(b0), "r"(b1));
}
__device__ __forceinline__ void cpasync16(uint32_t dst, const void* src) {
    asm volatile("cp.async.cg.shared.global [%0], [%1], 16;" :: "r"(dst), "l"(src) : "memory");
}
__device__ __forceinline__ void cpcommit() {
    asm volatile("cp.async.commit_group;" ::: "memory");
}
__device__ __forceinline__ void cpwait2() {
    asm volatile("cp.async.wait_group 2;" ::: "memory");
}

// ---------------- layer 0: fp32 -> bf16 planes ----------------
__global__ void layer0_kernel(const float* __restrict__ x, const float* __restrict__ w0,
                              __nv_bfloat16* __restrict__ oh_, __nv_bfloat16* __restrict__ ol_)
{
    __shared__ float xs[6][128];
    const int d   = blockIdx.x;
    const int tid = threadIdx.x;
#pragma unroll
    for (int i = 0; i < 3; i++) {
        int e = tid + i * 256;
        int ck = e >> 7, b = e & 127;
        int c = ck >> 1, k = ck & 1;
        xs[ck][b] = x[(b * 3 + c) * 1024 + 2 * d + k];
    }
    __syncthreads();
    const int b  = tid & 127;
    const int ohh = tid >> 7;
    const float2* w2 = (const float2*)w0;
    for (int o = ohh; o < 256; o += 2) {
        float acc = 0.f;
#pragma unroll
        for (int c = 0; c < 3; c++) {
            float2 wv = w2[(o * 3 + c) * 512 + d];
            acc += xs[c * 2 + 0][b] * wv.x + xs[c * 2 + 1][b] * wv.y;
        }
        float v = fmaxf(acc * 0.5773502691896258f, 0.f);
        __nv_bfloat16 h = __float2bfloat16(v);
        size_t idx = ((size_t)d * 128 + b) * 256 + o;
        oh_[idx] = h;
        ol_[idx] = __float2bfloat16(v - __bfloat162float(h));
    }
}

// ---------------- layers 1..9: warp-mma bf16x3, cp.async A-path ----------------
// A planes (p,b,c); w: (256,256,dl,2) fp32
// CTA: M=128(b) x N=128(o half) x K-slice (nst stages x 16 channels x 2 pos)
// smem stage tile (A or B): 128 rows x 128B, SW128 swizzle
//   row bytes: [0,32)=k0 hi, [32,64)=k1 hi, [64,96)=k0 lo, [96,128)=k1 lo
//   (kappa_local = k*16 + c_local; identical ldsm addressing as before)
// A: 4-deep cp.async ring (64KB). B: 2-deep register-converted (32KB).
#define SMEM_BYTES 98304

__global__ __launch_bounds__(256, 1)
void lc_mma(const __nv_bfloat16* __restrict__ gh, const __nv_bfloat16* __restrict__ gl,
            const float* __restrict__ w,
            __nv_bfloat16* __restrict__ oh_, __nv_bfloat16* __restrict__ ol_,
            int dl, int nst, float scale, int partial)
{
    extern __shared__ __align__(1024) char smem[];
    const uint32_t sb = s2u(smem);
    const int tid  = threadIdx.x;
    const int wid  = tid >> 5, lane = tid & 31;
    const int oh   = blockIdx.x;
    const int d    = blockIdx.y;
    const int s    = blockIdx.z;
    const int cbase = s * nst * 16;            // channel base of this K slice

    // ---- loader roles: row r (0..127), channel-half h (0..1) ----
    const int r = tid >> 1;
    const int h = tid & 1;
    const uint32_t rowb = (uint32_t)r * 128, xsw = (uint32_t)(r & 7) << 4;
    // byte base for (k, plane): k*32 + plane*64 + h*16, swizzled
    const uint32_t offs[4] = {
        rowb + ((0u * 32 + 0u * 64 + (uint32_t)h * 16) ^ xsw),   // k0 hi
        rowb + ((1u * 32 + 0u * 64 + (uint32_t)h * 16) ^ xsw),   // k1 hi
        rowb + ((0u * 32 + 1u * 64 + (uint32_t)h * 16) ^ xsw),   // k0 lo
        rowb + ((1u * 32 + 1u * 64 + (uint32_t)h * 16) ^ xsw)    // k1 lo
    };

    // A gmem row bases (both positions, both planes)
    const size_t arow0 = ((size_t)(2 * d) * 128 + r) * 256;
    const size_t arow1 = arow0 + 128 * 256;
    const __nv_bfloat16* asrc[4] = { gh + arow0, gh + arow1, gl + arow0, gl + arow1 };
    // asrc index: (plane*2 + pos) ; matches offs index (k=pos): offs[plane*2+pos]? careful:
    // offs[0]=k0 hi, offs[1]=k1 hi, offs[2]=k0 lo, offs[3]=k1 lo -> src pos = idx&1, plane = idx>>1. OK.

    // B gmem
    const float2* w2  = (const float2*)w;
    const size_t  wrow = (size_t)(oh * 128 + r) * 256;

    // smem bases
    const uint32_t Abase = sb;                 // 4 x 16KB ring
    const uint32_t Bbase = sb + 65536;         // 2 x 16KB

    // ---- compute roles: 2x4 warps, warp tile 64x32 ----
    const int mh = wid & 1, nq = wid >> 1;
    const uint32_t co = (uint32_t)(lane >> 4) * 16;
    const uint32_t xa = (uint32_t)(lane & 7) << 4;
    uint32_t rA[4], rB[2];
#pragma unroll
    for (int mi = 0; mi < 4; mi++) rA[mi] = (uint32_t)(mh * 64 + mi * 16 + (lane & 15)) * 128;
#pragma unroll
    for (int bj = 0; bj < 2; bj++) rB[bj] = (uint32_t)(nq * 32 + bj * 16 + (lane & 15)) * 128;

    float D[4][4][4];
#pragma unroll
    for (int i = 0; i < 4; i++)
#pragma unroll
        for (int j = 0; j < 4; j++)
#pragma unroll
            for (int q = 0; q < 4; q++) D[i][j][q] = 0.f;

    float2 bv[2][8];   // B register staging, 2 slots

    auto a_issue = [&](int t, int slot) {
        const int c0 = cbase + t * 16 + 8 * h;
        const uint32_t dstb = Abase + (uint32_t)slot * 16384;
#pragma unroll
        for (int i = 0; i < 4; i++)
            cpasync16(dstb + offs[i], asrc[i] + c0);
    };
    auto b_load = [&](int t, int slot) {
        const int c0 = cbase + t * 16 + 8 * h;
#pragma unroll
        for (int j = 0; j < 8; j++)
            bv[slot][j] = w2[(wrow + (size_t)(c0 + j)) * dl + d];
    };
    auto b_store = [&](int slot, int buf) {
        uint32_t H0[4], H1[4], L0[4], L1[4];
#pragma unroll
        for (int jj = 0; jj < 4; jj++) {
            split2(bv[slot][2 * jj].x, bv[slot][2 * jj + 1].x, H0[jj], L0[jj]);
            split2(bv[slot][2 * jj].y, bv[slot][2 * jj + 1].y, H1[jj], L1[jj]);
        }
        const uint32_t bb = Bbase + (uint32_t)buf * 16384;
        asm volatile("st.shared.v4.b32 [%0], {%1,%2,%3,%4};" :: "r"(bb + offs[0]), "r"(H0[0]), "r"(H0[1]), "r"(H0[2]), "r"(H0[3]));
        asm volatile("st.shared.v4.b32 [%0], {%1,%2,%3,%4};" :: "r"(bb + offs[1]), "r"(H1[0]), "r"(H1[1]), "r"(H1[2]), "r"(H1[3]));
        asm volatile("st.shared.v4.b32 [%0], {%1,%2,%3,%4};" :: "r"(bb + offs[2]), "r"(L0[0]), "r"(L0[1]), "r"(L0[2]), "r"(L0[3]));
        asm volatile("st.shared.v4.b32 [%0], {%1,%2,%3,%4};" :: "r"(bb + offs[3]), "r"(L1[0]), "r"(L1[1]), "r"(L1[2]), "r"(L1[3]));
    };

    // ---- prologue: A stages 0..2 (3 committed groups), B stage 0 ----
#pragma unroll
    for (int ps = 0; ps < 3; ps++) {
        if (ps < nst) a_issue(ps, ps);
        cpcommit();
    }
    b_load(0, 0);

    // ---- main loop ----
    for (int t = 0; t < nst; t++) {
        const int buf = t & 1;
        b_store(buf, buf);
        if (t + 1 < nst) b_load(t + 1, buf ^ 1);
        cpwait2();                      // A stage t resident
        __syncthreads();                // B visible; all warps past MMA(t-1)
        if (t + 3 < nst) a_issue(t + 3, (t + 3) & 3);
        cpcommit();

        const uint32_t ab = Abase + (uint32_t)(t & 3) * 16384;
        const uint32_t bb = Bbase + (uint32_t)buf * 16384;
#pragma unroll
        for (int kk = 0; kk < 2; kk++) {
            uint32_t Ahf[4][4], Alf[4][4], Bhf[2][4], Blf[2][4];
            const uint32_t khi = (uint32_t)(32 * kk) + co;
            const uint32_t klo = khi + 64;
#pragma unroll
            for (int mi = 0; mi < 4; mi++) {
                ldsm4(Ahf[mi], ab + rA[mi] + (khi ^ xa));
                ldsm4(Alf[mi], ab + rA[mi] + (klo ^ xa));
            }
#pragma unroll
            for (int bj = 0; bj < 2; bj++) {
                ldsm4(Bhf[bj], bb + rB[bj] + (khi ^ xa));
                ldsm4(Blf[bj], bb + rB[bj] + (klo ^ xa));
            }
#pragma unroll
            for (int mi = 0; mi < 4; mi++) {
#pragma unroll
                for (int nj = 0; nj < 4; nj++) {
                    const int bt = nj >> 1, bs = nj & 1;
                    mma16816(D[mi][nj], Ahf[mi], Bhf[bt][bs], Bhf[bt][bs + 2]);
                    mma16816(D[mi][nj], Alf[mi], Bhf[bt][bs], Bhf[bt][bs + 2]);
                    mma16816(D[mi][nj], Ahf[mi], Blf[bt][bs], Blf[bt][bs + 2]);
                }
            }
        }
        __syncthreads();                // MMA(t) done before B/A overwrites next iter
    }

    // ---- epilogue ----
    const int colq = nq * 32 + 2 * (lane & 3);
    if (partial) {
        float* pp = g_part + ((size_t)(s * 2 + oh) * dl + d) * 16384;
#pragma unroll
        for (int mi = 0; mi < 4; mi++) {
            const int b0 = mh * 64 + mi * 16 + (lane >> 2);
#pragma unroll
            for (int nj = 0; nj < 4; nj++) {
                const int col = colq + nj * 8;
                *(float2*)(pp + (size_t)b0 * 128 + col)       = make_float2(D[mi][nj][0], D[mi][nj][1]);
                *(float2*)(pp + (size_t)(b0 + 8) * 128 + col) = make_float2(D[mi][nj][2], D[mi][nj][3]);
            }
        }
    } else {
#pragma unroll
        for (int mi = 0; mi < 4; mi++) {
            const int b0 = mh * 64 + mi * 16 + (lane >> 2);
#pragma unroll
            for (int nj = 0; nj < 4; nj++) {
                const int col = oh * 128 + colq + nj * 8;
                float v00 = fmaxf(D[mi][nj][0] * scale, 0.f);
                float v01 = fmaxf(D[mi][nj][1] * scale, 0.f);
                float v10 = fmaxf(D[mi][nj][2] * scale, 0.f);
                float v11 = fmaxf(D[mi][nj][3] * scale, 0.f);
                uint32_t h0, l0, h1, l1;
                split2(v00, v01, h0, l0);
                split2(v10, v11, h1, l1);
                size_t i0 = ((size_t)d * 128 + b0) * 256 + col;
                size_t i1 = i0 + 8 * 256;
                *(uint32_t*)(oh_ + i0) = h0;  *(uint32_t*)(ol_ + i0) = l0;
                *(uint32_t*)(oh_ + i1) = h1;  *(uint32_t*)(ol_ + i1) = l1;
            }
        }
    }
}

// ---------------- split-K reduce + relu -> bf16 planes ----------------
__global__ void reduce_relu_kernel(const float* __restrict__ part,
                                   __nv_bfloat16* __restrict__ oh_, __nv_bfloat16* __restrict__ ol_,
                                   int n, int dl, int S, float scale)
{
    int idx = blockIdx.x * 256 + threadIdx.x;
    if (idx >= n) return;
    const int o  = idx & 255;
    const int b  = (idx >> 8) & 127;
    const int dd = idx >> 15;
    const int ohh = o >> 7, ol = o & 127;
    float sum = 0.f;
    for (int si = 0; si < S; si++)
        sum += part[((size_t)(si * 2 + ohh) * dl + dd) * 16384 + b * 128 + ol];
    float v = fmaxf(sum * scale, 0.f);
    __nv_bfloat16 hh = __float2bfloat16(v);
    oh_[idx] = hh;
    ol_[idx] = __float2bfloat16(v - __bfloat162float(hh));
}

// ---------------- head ----------------
__global__ void head_kernel(const __nv_bfloat16* __restrict__ ah, const __nv_bfloat16* __restrict__ al,
                            const float* __restrict__ beta, float* __restrict__ out)
{
    const int t = blockIdx.x;
    const int b = threadIdx.x;
    float s = 0.f;
#pragma unroll 8
    for (int o = 0; o < 256; o++) {
        float v = __bfloat162float(ah[b * 256 + o]) + __bfloat162float(al[b * 256 + o]);
        s += v * __ldg(&beta[o * 10 + t]);
    }
    out[b * 10 + t] = s * (1.0f / 256.0f);
}

// ---------------- launch ----------------
extern "C" void kernel_launch(void* const* d_in, const int* in_sizes, int n_in,
                              void* d_out, int out_size)
{
    const float* x = (const float*)d_in[0];
    const float* wl[10];
    for (int l = 0; l < 10; l++) wl[l] = (const float*)d_in[1 + l];
    const float* beta = (const float*)d_in[11];
    float* out = (float*)d_out;

    __nv_bfloat16 *hA, *lA, *hB, *lB;
    float* part;
    cudaGetSymbolAddress((void**)&hA, g_hA);
    cudaGetSymbolAddress((void**)&lA, g_lA);
    cudaGetSymbolAddress((void**)&hB, g_hB);
    cudaGetSymbolAddress((void**)&lB, g_lB);
    cudaGetSymbolAddress((void**)&part, g_part);

    cudaFuncSetAttribute(lc_mma, cudaFuncAttributeMaxDynamicSharedMemorySize, SMEM_BYTES);

    layer0_kernel<<<512, 256>>>(x, wl[0], hA, lA);

    __nv_bfloat16 *curH = hA, *curL = lA, *nxtH = hB, *nxtL = lB;
    int dl = 256;
    const float scale = 0.0625f;
    for (int l = 1; l <= 9; l++) {
        int S;
        if (dl >= 128)      S = 1;
        else if (dl == 64)  S = 2;
        else if (dl == 32)  S = 4;
        else if (dl >= 8)   S = 8;
        else                S = 16;
        const int nst = 16 / S;
        if (S == 1) {
            lc_mma<<<dim3(2, dl, 1), 256, SMEM_BYTES>>>(curH, curL, wl[l], nxtH, nxtL, dl, nst, scale, 0);
        } else {
            lc_mma<<<dim3(2, dl, S), 256, SMEM_BYTES>>>(curH, curL, wl[l], nullptr, nullptr, dl, nst, scale, 1);
            const int n = dl * 32768;
            reduce_relu_kernel<<<(n + 255) / 256, 256>>>(part, nxtH, nxtL, n, dl, S, scale);
        }
        __nv_bfloat16* t;
        t = curH; curH = nxtH; nxtH = t;
        t = curL; curL = nxtL; nxtL = t;
        dl >>= 1;
    }

    head_kernel<<<10, 128>>>(curH, curL, beta, out);
}